// round 1
// baseline (speedup 1.0000x reference)
#include <cuda_runtime.h>

typedef unsigned long long ull;

// Packed complex coefficients U[ch][k], ch=0..15, k=0..8 (re,im) as f32x2
__device__ ull g_coef[144];

__device__ __forceinline__ ull pack2(float a, float b) {
    ull r;
    asm("mov.b64 %0, {%1, %2};" : "=l"(r) : "f"(a), "f"(b));
    return r;
}
__device__ __forceinline__ void unpack2(ull v, float& a, float& b) {
    asm("mov.b64 {%0, %1}, %2;" : "=f"(a), "=f"(b) : "l"(v));
}
__device__ __forceinline__ void ffma2(ull& d, ull a, ull b) {
    asm("fma.rn.f32x2 %0, %1, %2, %0;" : "+l"(d) : "l"(a), "l"(b));
}

// ---------------------------------------------------------------------------
// Setup: build the 16x16 StronglyEntanglingLayers unitary from weights (2,4,3)
// and store the first 9 columns (patch dim) of each row, packed (re,im).
// 256 threads, one matrix element each.
// ---------------------------------------------------------------------------
__global__ void build_unitary_kernel(const float* __restrict__ w) {
    __shared__ float2 cur[16][16];
    __shared__ float2 Lm[16][16];
    __shared__ float2 tmp[16][16];
    int t = threadIdx.x;
    int i = t >> 4, j = t & 15;

    cur[i][j] = make_float2(i == j ? 1.f : 0.f, 0.f);
    __syncthreads();

#pragma unroll 1
    for (int l = 0; l < 2; l++) {
        // Layer matrix element: kron of 4 Rot(phi,theta,omega) gates; wire 0 = MSB
        float2 v = make_float2(1.f, 0.f);
        for (int wi = 0; wi < 4; wi++) {
            float phi = w[(l * 4 + wi) * 3 + 0];
            float th  = w[(l * 4 + wi) * 3 + 1];
            float om  = w[(l * 4 + wi) * 3 + 2];
            int bi = (i >> (3 - wi)) & 1;
            int bj = (j >> (3 - wi)) & 1;
            float sh, chf;
            sincosf(0.5f * th, &sh, &chf);
            float mag, phs;
            if (!bi && !bj)      { mag =  chf; phs = -0.5f * (phi + om); }
            else if (!bi &&  bj) { mag = -sh;  phs =  0.5f * (phi - om); }
            else if ( bi && !bj) { mag =  sh;  phs = -0.5f * (phi - om); }
            else                 { mag =  chf; phs =  0.5f * (phi + om); }
            float sp, cp;
            sincosf(phs, &sp, &cp);
            float2 e = make_float2(mag * cp, mag * sp);
            v = make_float2(v.x * e.x - v.y * e.y, v.x * e.y + v.y * e.x);
        }
        Lm[i][j] = v;
        __syncthreads();

        // tmp = Lm @ cur
        float2 acc = make_float2(0.f, 0.f);
        for (int k = 0; k < 16; k++) {
            float2 a = Lm[i][k], b = cur[k][j];
            acc.x += a.x * b.x - a.y * b.y;
            acc.y += a.x * b.y + a.y * b.x;
        }
        tmp[i][j] = acc;
        __syncthreads();

        // Apply CNOT ring as composed row permutation.
        // U <- C3 C2 C1 C0 tmp ; row i comes from tmp[p0[p1[p2[p3[i]]]]]
        int r = (l % 3) + 1;
        int q = i;
        for (int m = 3; m >= 0; m--) {
            int tt = (m + r) & 3;
            int cb = 1 << (3 - m), tb = 1 << (3 - tt);
            if (q & cb) q ^= tb;
        }
        cur[i][j] = tmp[q][j];
        __syncthreads();
    }

    if (j < 9) {
        float2 u = cur[i][j];
        g_coef[i * 9 + j] = pack2(u.x, u.y);
    }
}

// ---------------------------------------------------------------------------
// Main kernel. Each thread: a 4(x) x 2(y) pixel quad, all 16 channels.
// Block: 64 x 4 threads = full 256-wide row span, 8 rows.
// Grid: (1, 32 row-strips, 32 batches).
// out[b][ch][y][x] = min(8 * |U_ch . p|^2 / ||p||^2, 1)
// ---------------------------------------------------------------------------
__global__ __launch_bounds__(256, 2)
void qconv_kernel(const float* __restrict__ x, float* __restrict__ out) {
    __shared__ ull sW[144];
    int tid = threadIdx.y * 64 + threadIdx.x;
    if (tid < 144) sW[tid] = g_coef[tid];
    __syncthreads();

    const int b  = blockIdx.z;
    const int x0 = threadIdx.x * 4;                       // 0..252
    const int r0 = blockIdx.y * 8 + threadIdx.y * 2;      // 0..254

    const float* xin = x + (size_t)b * 65536;

    // Load 4 rows (r0-1 .. r0+2) x 6 cols (x0-1 .. x0+4), pad = 0.01
    float v[4][6];
#pragma unroll
    for (int i = 0; i < 4; i++) {
        int ry = r0 - 1 + i;
        if (ry >= 0 && ry < 256) {
            const float* rp = xin + ry * 256;
            float4 q = *(const float4*)(rp + x0);
            v[i][1] = q.x; v[i][2] = q.y; v[i][3] = q.z; v[i][4] = q.w;
            v[i][0] = (x0 > 0)   ? rp[x0 - 1] : 0.01f;
            v[i][5] = (x0 < 252) ? rp[x0 + 4] : 0.01f;
        } else {
#pragma unroll
            for (int c = 0; c < 6; c++) v[i][c] = 0.01f;
        }
    }

    // ||p||^2 per pixel via separable row sums, then 8/s (guarded)
    float h[4][4];
#pragma unroll
    for (int i = 0; i < 4; i++) {
        float sq[6];
#pragma unroll
        for (int c = 0; c < 6; c++) sq[c] = v[i][c] * v[i][c];
#pragma unroll
        for (int c = 0; c < 4; c++) h[i][c] = sq[c] + sq[c + 1] + sq[c + 2];
    }
    float inv[2][4];
#pragma unroll
    for (int r = 0; r < 2; r++)
#pragma unroll
        for (int c = 0; c < 4; c++) {
            float s = h[r][c] + h[r + 1][c] + h[r + 2][c];
            inv[r][c] = (s > 1e-24f) ? __fdividef(8.0f, s) : 0.0f;
        }

    // Broadcast-packed patch values for f32x2 FMAs
    ull pp[4][6];
#pragma unroll
    for (int i = 0; i < 4; i++)
#pragma unroll
        for (int c = 0; c < 6; c++) pp[i][c] = pack2(v[i][c], v[i][c]);

    float* ob = out + (size_t)b * 16 * 65536 + (size_t)r0 * 256 + x0;

#pragma unroll 1
    for (int ch = 0; ch < 16; ch++) {
        ull C[9];
#pragma unroll
        for (int k = 0; k < 9; k++) C[k] = sW[ch * 9 + k];

        ull acc[2][4];
#pragma unroll
        for (int r = 0; r < 2; r++)
#pragma unroll
            for (int c = 0; c < 4; c++) acc[r][c] = 0ULL;

#pragma unroll
        for (int dr = 0; dr < 3; dr++)
#pragma unroll
            for (int dc = 0; dc < 3; dc++) {
                ull cf = C[dr * 3 + dc];
#pragma unroll
                for (int r = 0; r < 2; r++)
#pragma unroll
                    for (int c = 0; c < 4; c++)
                        ffma2(acc[r][c], cf, pp[r + dr][c + dc]);
            }

#pragma unroll
        for (int r = 0; r < 2; r++) {
            float res[4];
#pragma unroll
            for (int c = 0; c < 4; c++) {
                float re, im;
                unpack2(acc[r][c], re, im);
                float mag = re * re + im * im;
                res[c] = fminf(mag * inv[r][c], 1.0f);
            }
            *(float4*)(ob + (size_t)ch * 65536 + (size_t)r * 256) =
                make_float4(res[0], res[1], res[2], res[3]);
        }
    }
}

extern "C" void kernel_launch(void* const* d_in, const int* in_sizes, int n_in,
                              void* d_out, int out_size) {
    const float* x = (const float*)d_in[0];        // (32,1,256,256) fp32
    const float* w = (const float*)d_in[1];        // (2,4,3) fp32
    float* out = (float*)d_out;                    // (32,16,256,256) fp32

    build_unitary_kernel<<<1, 256>>>(w);

    dim3 block(64, 4, 1);
    dim3 grid(1, 32, 32);
    qconv_kernel<<<grid, block>>>(x, out);
}